// round 12
// baseline (speedup 1.0000x reference)
#include <cuda_runtime.h>
#include <cuda_fp16.h>
#include <cstdint>
#include <cstddef>

#define NROWS 8192
#define DIN   2048
#define DOUT  2048

#define BM 128
#define BN 128
#define BK 32
#define NCHUNK (DIN / BK)          // 64
#define NT_M (NROWS / BM)          // 64
#define NT_N (DOUT / BN)           // 16
#define NSTAGE 3

#define PITCH 40                   // halves per smem row (80B) -> conflict-free ldmatrix
#define A_TILE_BYTES (BM * PITCH * 2)            // 10240
#define SMEM_TOTAL   (NSTAGE * A_TILE_BYTES)     // 30720 (x2 CTAs = 61440/SM)

#define MF_STRIDE (16 * PITCH * 2)               // 1280 B per 16-row frag step
#define KH_STRIDE 32                             // 16 halves per k-half

#define NKW (DIN / 16)                           // 128 code-words along K

__device__ __align__(16) __half   g_Ah[(size_t)NROWS * DIN];     // 32 MB fp16 A
__device__ __align__(16) uint32_t g_Bc2[(size_t)NKW * DOUT];     // 1 MB codes [kword][n]

static __device__ __forceinline__ uint32_t smem_u32(const void* p) {
    uint32_t a;
    asm("{ .reg .u64 t; cvta.to.shared.u64 t, %1; cvt.u32.u64 %0, t; }" : "=r"(a) : "l"(p));
    return a;
}
static __device__ __forceinline__ uint32_t pack2(float a, float b) {
    __half2 h = __floats2half2_rn(a, b);
    return *reinterpret_cast<uint32_t*>(&h);
}
static __device__ __forceinline__ void cp16(uint32_t dst, const void* src) {
    asm volatile("cp.async.cg.shared.global [%0], [%1], 16;" :: "r"(dst), "l"(src));
}
#define CP_COMMIT() asm volatile("cp.async.commit_group;" ::: "memory")
#define CP_WAIT1()  asm volatile("cp.async.wait_group 1;" ::: "memory")

#define LDSM_X4(r0, r1, r2, r3, addr) \
    asm volatile("ldmatrix.sync.aligned.m8n8.x4.shared.b16 {%0,%1,%2,%3}, [%4];" \
                 : "=r"(r0), "=r"(r1), "=r"(r2), "=r"(r3) : "r"(addr))

#define MMA16816(c, a, b0, b1) \
    asm volatile("mma.sync.aligned.m16n8k16.row.col.f32.f16.f16.f32 " \
                 "{%0,%1,%2,%3}, {%4,%5,%6,%7}, {%8,%9}, {%0,%1,%2,%3};" \
                 : "+f"((c)[0]), "+f"((c)[1]), "+f"((c)[2]), "+f"((c)[3]) \
                 : "r"((a)[0]), "r"((a)[1]), "r"((a)[2]), "r"((a)[3]), \
                   "r"(b0), "r"(b1))

// decode nibble (2 codes) -> packed half2 {code0, code1}; codes: 0->0, 1->+1, 3->-1
// byte table: idx0=0x00, idx1=0x3C, idx2=0x00, idx3=0xBC  (value 0xBC003C00)
static __device__ __forceinline__ uint32_t dec4(uint32_t t) {
    const uint32_t sel = ((t & 3u) << 4) | ((t & 0xCu) << 10);
    uint32_t r;
    asm("prmt.b32 %0, %1, %2, %3;" : "=r"(r) : "r"(0xBC003C00u), "r"(0u), "r"(sel));
    return r;
}

// ---------------- fused prep: A convert + B 2-bit code pack ----------------
__global__ __launch_bounds__(256) void prep_kernel(const float* __restrict__ A,
                                                   const float* __restrict__ W) {
    __shared__ unsigned char s[32][33];
    if (blockIdx.x < NROWS) {
        const int m = blockIdx.x;
        const size_t i = (size_t)m * DIN + threadIdx.x * 8;
        const float4* src = reinterpret_cast<const float4*>(A + i);
        float4 f0 = src[0], f1 = src[1];
        uint4 u;
        u.x = pack2(f0.x, f0.y); u.y = pack2(f0.z, f0.w);
        u.z = pack2(f1.x, f1.y); u.w = pack2(f1.z, f1.w);
        *reinterpret_cast<uint4*>(g_Ah + i) = u;
    } else {
        // codes: W[k][n] -> g_Bc2[k/16][n], 16 k per word, 2 bits each
        const int bid = (int)blockIdx.x - NROWS;
        const int nb = bid % (DOUT / 32);
        const int kb = bid / (DOUT / 32);
        const int tx = threadIdx.x & 31, ty = threadIdx.x >> 5;
        #pragma unroll
        for (int j = 0; j < 4; j++) {
            const int kk = ty + j * 8;
            const float w = W[(size_t)(kb * 32 + kk) * DOUT + nb * 32 + tx];
            s[kk][tx] = (unsigned char)(w > 0.f ? 1 : (w < 0.f ? 3 : 0));
        }
        __syncthreads();
        if (threadIdx.x < 64) {
            const int nn = (int)threadIdx.x >> 1;
            const int half = (int)threadIdx.x & 1;
            uint32_t w = 0;
            #pragma unroll
            for (int j = 0; j < 16; j++)
                w |= ((uint32_t)s[half * 16 + j][nn]) << (2 * j);
            g_Bc2[(size_t)(kb * 2 + half) * DOUT + nb * 32 + nn] = w;
        }
    }
}

// -------------------------------- GEMM --------------------------------
// 128x128, 8 warps (4m x 2n). A: 3-stage cp.async + LDSM. B: in-register decode
// from 2-bit codes (no B smem traffic at all), one kh-phase LDG lookahead.
__global__ __launch_bounds__(256, 2) void gemm_kernel(const float* __restrict__ bias,
                                                      float* __restrict__ out) {
    extern __shared__ __align__(16) unsigned char smem[];
    const uint32_t sbase = smem_u32(smem);

    const int tid = threadIdx.x;
    const int lid = tid & 31;
    const int warp = tid >> 5;
    const int warp_m = warp & 3;
    const int warp_n = warp >> 2;
    const int mt = (int)blockIdx.x & 63;
    const int nt = (int)blockIdx.x >> 6;
    const int m0 = mt * BM, n0 = nt * BN;

    const int g = lid >> 3, lr = lid & 7;
    const uint32_t a_base = sbase +
        (uint32_t)(((warp_m * 32 + (g & 1) * 8 + lr) * PITCH + (g >> 1) * 8) * 2);
    const uint32_t shl = (uint32_t)(lid & 3) * 4;   // nibble shift for this lane

    float c[2][8][4];
    #pragma unroll
    for (int mf = 0; mf < 2; mf++)
        #pragma unroll
        for (int nf = 0; nf < 8; nf++)
            #pragma unroll
            for (int q = 0; q < 4; q++) c[mf][nf][q] = 0.f;

    const __half* gA = g_Ah + (size_t)m0 * DIN;

    // A cp.async: 512 16B-chunks per stage, 2 per thread
    auto issue_A = [&](int stage, int kbase) {
        const uint32_t so = (uint32_t)stage * A_TILE_BYTES;
        #pragma unroll
        for (int j = 0; j < 2; j++) {
            const int cidx = tid + j * 256;
            const int row = cidx >> 2, seg = cidx & 3;
            cp16(sbase + so + (uint32_t)(row * PITCH + seg * 8) * 2,
                 gA + (size_t)row * DIN + kbase + seg * 8);
        }
    };

    // code-word pointer: phase ph = kc*2+kh; word[ph][n], n = n0 + warp_n*64 + nf2*16 + sub*8 + lid/4
    const uint32_t* gw = g_Bc2 + (size_t)(n0 + warp_n * 64 + (lid >> 2));

    issue_A(0, 0);
    CP_COMMIT();
    issue_A(1, BK);
    CP_COMMIT();

    uint32_t wA[8], wB[8];
    #pragma unroll
    for (int j = 0; j < 8; j++)                 // phase 0 words
        wA[j] = gw[(j >> 1) * 16 + (j & 1) * 8];
    gw += DOUT;

    #define DECODE_MMA(WARR) \
        { \
            uint32_t a0[4], a1[4]; \
            LDSM_X4(a0[0], a0[1], a0[2], a0[3], ak + 0 * MF_STRIDE); \
            LDSM_X4(a1[0], a1[1], a1[2], a1[3], ak + 1 * MF_STRIDE); \
            _Pragma("unroll") \
            for (int nf2 = 0; nf2 < 4; nf2++) { \
                const uint32_t ta = WARR[nf2 * 2 + 0] >> shl; \
                const uint32_t tb = WARR[nf2 * 2 + 1] >> shl; \
                const uint32_t b0 = dec4(ta), b1 = dec4(ta >> 16); \
                const uint32_t b2 = dec4(tb), b3 = dec4(tb >> 16); \
                MMA16816(c[0][nf2 * 2 + 0], a0, b0, b1); \
                MMA16816(c[1][nf2 * 2 + 0], a1, b0, b1); \
                MMA16816(c[0][nf2 * 2 + 1], a0, b2, b3); \
                MMA16816(c[1][nf2 * 2 + 1], a1, b2, b3); \
            } \
        }

    for (int kc = 0; kc < NCHUNK; kc++) {
        const int stage = kc % NSTAGE;
        CP_WAIT1();
        __syncthreads();

        const uint32_t aoff = a_base + (uint32_t)stage * A_TILE_BYTES;

        // kh = 0: prefetch words for kh=1, compute from wA
        #pragma unroll
        for (int j = 0; j < 8; j++)
            wB[j] = gw[(j >> 1) * 16 + (j & 1) * 8];
        gw += DOUT;
        {
            const uint32_t ak = aoff;
            DECODE_MMA(wA);
        }

        // spread the A STS burst into the compute phase
        if (kc + 2 < NCHUNK) issue_A((kc + 2) % NSTAGE, (kc + 2) * BK);
        CP_COMMIT();

        // kh = 1: prefetch words for next kc's kh=0, compute from wB
        if (kc + 1 < NCHUNK) {
            #pragma unroll
            for (int j = 0; j < 8; j++)
                wA[j] = gw[(j >> 1) * 16 + (j & 1) * 8];
            gw += DOUT;
        }
        {
            const uint32_t ak = aoff + KH_STRIDE;
            DECODE_MMA(wB);
        }
    }

    // epilogue: bias + sector-aligned float2 stores
    #pragma unroll
    for (int nf = 0; nf < 8; nf++) {
        const int col = n0 + warp_n * 64 + nf * 8 + (lid & 3) * 2;
        const float2 bv = *reinterpret_cast<const float2*>(bias + col);
        #pragma unroll
        for (int mf = 0; mf < 2; mf++) {
            const int r0 = m0 + warp_m * 32 + mf * 16 + (lid >> 2);
            float2 v0 = make_float2(c[mf][nf][0] + bv.x, c[mf][nf][1] + bv.y);
            float2 v1 = make_float2(c[mf][nf][2] + bv.x, c[mf][nf][3] + bv.y);
            *reinterpret_cast<float2*>(out + (size_t)r0 * DOUT + col) = v0;
            *reinterpret_cast<float2*>(out + (size_t)(r0 + 8) * DOUT + col) = v1;
        }
    }
}

extern "C" void kernel_launch(void* const* d_in, const int* in_sizes, int n_in,
                              void* d_out, int out_size) {
    const float* A = (const float*)d_in[0];
    const float* W = (const float*)d_in[1];
    const float* b = (const float*)d_in[2];
    float* out = (float*)d_out;

    cudaFuncSetAttribute(gemm_kernel, cudaFuncAttributeMaxDynamicSharedMemorySize, SMEM_TOTAL);

    prep_kernel<<<NROWS + (DIN / 32) * (DOUT / 32), 256>>>(A, W);
    gemm_kernel<<<NT_M * NT_N, 256, SMEM_TOTAL>>>(b, out);
}